// round 3
// baseline (speedup 1.0000x reference)
#include <cuda_runtime.h>

#define NN   8
#define CC   256
#define HH   128
#define WW   128
#define HWSZ 16384
#define NBOX 20
#define TEMP     0.5f
#define INVTEMP  2.0f
#define ALPHA    1e-3f
#define BETA     5e-4f
#define GAMMA    1e-3f
#define LAMB     5e-6f
#define IMGF     1024.0f
#define LN_EPS   1e-5f

// ---------------- scratch (static device memory; no allocs) ----------------
__device__ float g_fea_s[NN * HWSZ];
__device__ float g_fea_t[NN * HWSZ];
__device__ float g_cm_s [NN * HWSZ];
__device__ float g_cm_t [NN * HWSZ];
__device__ float g_sm_s [NN * HWSZ];
__device__ float g_sm_t [NN * HWSZ];
__device__ float g_wfg  [NN * HWSZ];
__device__ float g_wbg  [NN * HWSZ];
__device__ float g_ch_s [NN * CC];
__device__ float g_ch_t [NN * CC];
__device__ float g_Ct   [NN * CC];
__device__ float g_ctx_s[NN * CC];
__device__ float g_ctx_t[NN * CC];
__device__ float g_rowd [NN * CC];
__device__ float g_fgsum;
__device__ float g_bgsum;
__device__ float g_d2sum;
__device__ float g_maskloss;

// ---------------- reduction helpers ----------------
__device__ __forceinline__ float warpsum(float v) {
#pragma unroll
    for (int o = 16; o > 0; o >>= 1) v += __shfl_xor_sync(0xffffffffu, v, o);
    return v;
}
__device__ __forceinline__ float warpmax(float v) {
#pragma unroll
    for (int o = 16; o > 0; o >>= 1) v = fmaxf(v, __shfl_xor_sync(0xffffffffu, v, o));
    return v;
}
__device__ __forceinline__ float blocksum(float v, float* sbuf) {
    int tid = threadIdx.x, lane = tid & 31, warp = tid >> 5;
    int nw = blockDim.x >> 5;
    v = warpsum(v);
    if (lane == 0) sbuf[warp] = v;
    __syncthreads();
    if (warp == 0) {
        float r = (lane < nw) ? sbuf[lane] : 0.0f;
        r = warpsum(r);
        if (lane == 0) sbuf[0] = r;
    }
    __syncthreads();
    float r = sbuf[0];
    __syncthreads();
    return r;
}
__device__ __forceinline__ float blockmax(float v, float* sbuf) {
    int tid = threadIdx.x, lane = tid & 31, warp = tid >> 5;
    int nw = blockDim.x >> 5;
    v = warpmax(v);
    if (lane == 0) sbuf[warp] = v;
    __syncthreads();
    if (warp == 0) {
        float r = (lane < nw) ? sbuf[lane] : -3.4e38f;
        r = warpmax(r);
        if (lane == 0) sbuf[0] = r;
    }
    __syncthreads();
    float r = sbuf[0];
    __syncthreads();
    return r;
}

// ---------------- init: zero the atomically-accumulated scratch --------------
__global__ void __launch_bounds__(256) k_init() {
    int i = blockIdx.x * blockDim.x + threadIdx.x;
    if (i < NN * CC) {
        g_ch_s[i] = 0.f; g_ch_t[i] = 0.f;
        g_ctx_s[i] = 0.f; g_ctx_t[i] = 0.f; g_rowd[i] = 0.f;
    }
    if (i == 0) { g_fgsum = 0.f; g_bgsum = 0.f; g_d2sum = 0.f; g_maskloss = 0.f; }
}

// ---------------- pass 1: one read of S,T -> per-pixel & per-channel stats ---
// grid (HWSZ/1024, NN), block 256. Each thread owns 4 contiguous pixels.
__global__ void __launch_bounds__(256) k_pass1(
        const float* __restrict__ S, const float* __restrict__ T,
        const float* __restrict__ wms, const float* __restrict__ bms,
        const float* __restrict__ wmt, const float* __restrict__ bmt) {
    __shared__ float sws[CC], swt[CC];
    int tid = threadIdx.x;
    sws[tid] = wms[tid];
    swt[tid] = wmt[tid];
    __syncthreads();

    int n  = blockIdx.y;
    int p  = blockIdx.x * 1024 + tid * 4;
    int lane = tid & 31;
    const float4* Sp = (const float4*)(S + (size_t)n * CC * HWSZ + p);
    const float4* Tp = (const float4*)(T + (size_t)n * CC * HWSZ + p);

    float4 feas = make_float4(0.f, 0.f, 0.f, 0.f);
    float4 feat = feas, cms = feas, cmt = feas;

#pragma unroll 1
    for (int c0 = 0; c0 < CC; c0 += 4) {
        float4 sv[4], tv[4];
#pragma unroll
        for (int u = 0; u < 4; u++) {
            sv[u] = Sp[(size_t)(c0 + u) * (HWSZ / 4)];
            tv[u] = Tp[(size_t)(c0 + u) * (HWSZ / 4)];
        }
#pragma unroll
        for (int u = 0; u < 4; u++) {
            int c = c0 + u;
            float4 s = sv[u], t = tv[u];
            float4 as = make_float4(fabsf(s.x), fabsf(s.y), fabsf(s.z), fabsf(s.w));
            float4 at = make_float4(fabsf(t.x), fabsf(t.y), fabsf(t.z), fabsf(t.w));
            feas.x += as.x; feas.y += as.y; feas.z += as.z; feas.w += as.w;
            feat.x += at.x; feat.y += at.y; feat.z += at.z; feat.w += at.w;
            float ws = sws[c], wt = swt[c];
            cms.x = fmaf(s.x, ws, cms.x); cms.y = fmaf(s.y, ws, cms.y);
            cms.z = fmaf(s.z, ws, cms.z); cms.w = fmaf(s.w, ws, cms.w);
            cmt.x = fmaf(t.x, wt, cmt.x); cmt.y = fmaf(t.y, wt, cmt.y);
            cmt.z = fmaf(t.z, wt, cmt.z); cmt.w = fmaf(t.w, wt, cmt.w);
            float cps = as.x + as.y + as.z + as.w;
            float cpt = at.x + at.y + at.z + at.w;
            cps = warpsum(cps); cpt = warpsum(cpt);
            if (lane == 0) {
                atomicAdd(&g_ch_s[n * CC + c], cps);
                atomicAdd(&g_ch_t[n * CC + c], cpt);
            }
        }
    }
    int o = n * HWSZ + p;
    const float invC = 1.0f / (float)CC;
    float bs = bms[0], bt = bmt[0];
    *(float4*)(g_fea_s + o) = make_float4(feas.x * invC, feas.y * invC, feas.z * invC, feas.w * invC);
    *(float4*)(g_fea_t + o) = make_float4(feat.x * invC, feat.y * invC, feat.z * invC, feat.w * invC);
    *(float4*)(g_cm_s + o)  = make_float4(cms.x + bs, cms.y + bs, cms.z + bs, cms.w + bs);
    *(float4*)(g_cm_t + o)  = make_float4(cmt.x + bt, cmt.y + bt, cmt.z + bt, cmt.w + bt);
}

// ---------------- pass 2a: channel softmaxes + channel mask-loss term --------
// grid NN, block 256 (one thread per channel)
__global__ void __launch_bounds__(256) k_pass2a() {
    __shared__ float sbuf[32];
    int n = blockIdx.x, tid = threadIdx.x;
    const float sc = 1.0f / ((float)HWSZ * TEMP);
    float as = g_ch_s[n * CC + tid] * sc;
    float at = g_ch_t[n * CC + tid] * sc;
    float ms = blockmax(as, sbuf);
    float mt = blockmax(at, sbuf);
    float es = __expf(as - ms);
    float et = __expf(at - mt);
    float ss = blocksum(es, sbuf);
    float st = blocksum(et, sbuf);
    float Cs = (float)CC * es / ss;
    float Ct = (float)CC * et / st;
    g_Ct[n * CC + tid] = Ct;
    float d = blocksum(fabsf(Cs - Ct), sbuf);
    if (tid == 0) atomicAdd(&g_maskloss, d);
}

// ---------------- pass 2b: spatial softmaxes, box masks, weights -------------
// grid NN, block 512
__global__ void __launch_bounds__(512) k_pass2b(const float* __restrict__ gt) {
    __shared__ float sbuf[32];
    __shared__ float bhmin[NBOX], bhmax[NBOX], bwmin[NBOX], bwmax[NBOX], barea[NBOX];
    int n = blockIdx.x, tid = threadIdx.x;
    if (tid < NBOX) {
        const float* b = gt + ((size_t)n * NBOX + tid) * 4;
        float wmin = floorf(b[0] * ((float)WW / IMGF));
        float hmin = floorf(b[1] * ((float)HH / IMGF));
        float wmax = ceilf (b[2] * ((float)WW / IMGF));
        float hmax = ceilf (b[3] * ((float)HH / IMGF));
        bhmin[tid] = hmin; bhmax[tid] = hmax;
        bwmin[tid] = wmin; bwmax[tid] = wmax;
        barea[tid] = 1.0f / ((hmax + 1.0f - hmin) * (wmax + 1.0f - wmin));
    }
    __syncthreads();

    const float* feas = g_fea_s + n * HWSZ;
    const float* feat = g_fea_t + n * HWSZ;
    const float* cms  = g_cm_s  + n * HWSZ;
    const float* cmt  = g_cm_t  + n * HWSZ;

    // phase 1: maxes
    float m0 = -3.4e38f, m1 = -3.4e38f, m2 = -3.4e38f, m3 = -3.4e38f;
    for (int p = tid; p < HWSZ; p += 512) {
        m0 = fmaxf(m0, feas[p]); m1 = fmaxf(m1, feat[p]);
        m2 = fmaxf(m2, cms[p]);  m3 = fmaxf(m3, cmt[p]);
    }
    m0 = blockmax(m0, sbuf) * INVTEMP;
    m1 = blockmax(m1, sbuf) * INVTEMP;
    m2 = blockmax(m2, sbuf);
    m3 = blockmax(m3, sbuf);

    // phase 2: exp-sums + background pixel count
    float s0 = 0.f, s1 = 0.f, s2 = 0.f, s3 = 0.f, bgc = 0.f;
    for (int p = tid; p < HWSZ; p += 512) {
        s0 += __expf(feas[p] * INVTEMP - m0);
        s1 += __expf(feat[p] * INVTEMP - m1);
        s2 += __expf(cms[p] - m2);
        s3 += __expf(cmt[p] - m3);
        float h = (float)(p >> 7), w = (float)(p & 127);
        float mfg = 0.f;
#pragma unroll 1
        for (int b = 0; b < NBOX; b++) {
            bool in = (h >= bhmin[b]) && (h <= bhmax[b]) && (w >= bwmin[b]) && (w <= bwmax[b]);
            if (in) mfg = fmaxf(mfg, barea[b]);
        }
        if (mfg == 0.f) bgc += 1.f;
    }
    s0 = blocksum(s0, sbuf); s1 = blocksum(s1, sbuf);
    s2 = blocksum(s2, sbuf); s3 = blocksum(s3, sbuf);
    bgc = blocksum(bgc, sbuf);
    float invbg = (bgc > 0.f) ? (1.0f / bgc) : 0.f;
    float r0 = 1.0f / s0, r1 = 1.0f / s1, r2 = 1.0f / s2, r3 = 1.0f / s3;

    // phase 3: write weights, accumulate |S_s - S_t|
    float sd = 0.f;
    for (int p = tid; p < HWSZ; p += 512) {
        float Ss = (float)HWSZ * __expf(feas[p] * INVTEMP - m0) * r0;
        float St = (float)HWSZ * __expf(feat[p] * INVTEMP - m1) * r1;
        float ssm = __expf(cms[p] - m2) * r2;
        float stm = __expf(cmt[p] - m3) * r3;
        float h = (float)(p >> 7), w = (float)(p & 127);
        float mfg = 0.f;
#pragma unroll 1
        for (int b = 0; b < NBOX; b++) {
            bool in = (h >= bhmin[b]) && (h <= bhmax[b]) && (w >= bwmin[b]) && (w <= bwmax[b]);
            if (in) mfg = fmaxf(mfg, barea[b]);
        }
        float mbg = (mfg > 0.f) ? 0.f : invbg;
        int o = n * HWSZ + p;
        g_sm_s[o] = ssm;
        g_sm_t[o] = stm;
        g_wfg[o]  = St * mfg;
        g_wbg[o]  = St * mbg;
        sd += fabsf(Ss - St);
    }
    sd = blocksum(sd, sbuf);
    if (tid == 0) atomicAdd(&g_maskloss, sd);
}

// ---------------- pass 3: second read of S,T -> ctx, rowdiff, loss scalars ---
// grid (HWSZ/1024, NN), block 256
__global__ void __launch_bounds__(256) k_pass3(
        const float* __restrict__ S, const float* __restrict__ T) {
    __shared__ float sCt[CC];
    int tid = threadIdx.x;
    int n = blockIdx.y;
    sCt[tid] = g_Ct[n * CC + tid];
    __syncthreads();

    int p = blockIdx.x * 1024 + tid * 4;
    int o = n * HWSZ + p;
    int lane = tid & 31;
    float4 wfg = *(const float4*)(g_wfg + o);
    float4 wbg = *(const float4*)(g_wbg + o);
    float4 ssm = *(const float4*)(g_sm_s + o);
    float4 stm = *(const float4*)(g_sm_t + o);
    const float4* Sp = (const float4*)(S + (size_t)n * CC * HWSZ + p);
    const float4* Tp = (const float4*)(T + (size_t)n * CC * HWSZ + p);

    float fga = 0.f, bga = 0.f, d2a = 0.f;
#pragma unroll 1
    for (int c0 = 0; c0 < CC; c0 += 4) {
        float4 sv[4], tv[4];
#pragma unroll
        for (int u = 0; u < 4; u++) {
            sv[u] = Sp[(size_t)(c0 + u) * (HWSZ / 4)];
            tv[u] = Tp[(size_t)(c0 + u) * (HWSZ / 4)];
        }
#pragma unroll
        for (int u = 0; u < 4; u++) {
            int c = c0 + u;
            float4 s = sv[u], t = tv[u];
            float4 d = make_float4(s.x - t.x, s.y - t.y, s.z - t.z, s.w - t.w);
            float4 d2 = make_float4(d.x * d.x, d.y * d.y, d.z * d.z, d.w * d.w);
            float pcs = fmaf(s.x, ssm.x, fmaf(s.y, ssm.y, fmaf(s.z, ssm.z, s.w * ssm.w)));
            float pct = fmaf(t.x, stm.x, fmaf(t.y, stm.y, fmaf(t.z, stm.z, t.w * stm.w)));
            float prd = (d.x + d.y) + (d.z + d.w);
            d2a += (d2.x + d2.y) + (d2.z + d2.w);
            float ct = sCt[c];
            float pfg = fmaf(d2.x, wfg.x, fmaf(d2.y, wfg.y, fmaf(d2.z, wfg.z, d2.w * wfg.w)));
            float pbg = fmaf(d2.x, wbg.x, fmaf(d2.y, wbg.y, fmaf(d2.z, wbg.z, d2.w * wbg.w)));
            fga = fmaf(pfg, ct, fga);
            bga = fmaf(pbg, ct, bga);
            pcs = warpsum(pcs); pct = warpsum(pct); prd = warpsum(prd);
            if (lane == 0) {
                atomicAdd(&g_ctx_s[n * CC + c], pcs);
                atomicAdd(&g_ctx_t[n * CC + c], pct);
                atomicAdd(&g_rowd [n * CC + c], prd);
            }
        }
    }
    fga = warpsum(fga); bga = warpsum(bga); d2a = warpsum(d2a);
    if (lane == 0) {
        atomicAdd(&g_fgsum, fga);
        atomicAdd(&g_bgsum, bga);
        atomicAdd(&g_d2sum, d2a);
    }
}

// ---------------- pass 4: tiny MLPs + final scalar ---------------------------
// grid 1, block 256
__global__ void __launch_bounds__(256) k_pass4(
        const float* __restrict__ w1s, const float* __restrict__ b1s,
        const float* __restrict__ gs,  const float* __restrict__ bes,
        const float* __restrict__ w2s, const float* __restrict__ b2s,
        const float* __restrict__ w1t, const float* __restrict__ b1t,
        const float* __restrict__ gtl, const float* __restrict__ bet,
        const float* __restrict__ w2t, const float* __restrict__ b2t,
        float* __restrict__ out) {
    __shared__ float sy[256];
    __shared__ float swsum[8], swsq[8];
    __shared__ float sbuf[32];
    int tid = threadIdx.x, lane = tid & 31, warp = tid >> 5;
    int j = tid & 127;
    bool isT = (tid >= 128);
    const float* w1 = isT ? w1t : w1s;
    const float* b1 = isT ? b1t : b1s;
    const float* gg = isT ? gtl : gs;
    const float* bb = isT ? bet : bes;
    const float* w1row = w1 + (size_t)j * CC;

    float accx = 0.f, accd = 0.f;
    for (int n = 0; n < NN; n++) {
        const float* ctx = (isT ? g_ctx_t : g_ctx_s) + n * CC;
        float y = b1[j];
#pragma unroll 4
        for (int c = 0; c < CC; c++) y = fmaf(ctx[c], w1row[c], y);
        float v = warpsum(y), v2 = warpsum(y * y);
        if (lane == 0) { swsum[warp] = v; swsq[warp] = v2; }
        __syncthreads();
        int h0 = isT ? 4 : 0;
        float mean = (swsum[h0] + swsum[h0 + 1] + swsum[h0 + 2] + swsum[h0 + 3]) * (1.0f / 128.0f);
        float msq  = (swsq[h0] + swsq[h0 + 1] + swsq[h0 + 2] + swsq[h0 + 3]) * (1.0f / 128.0f);
        float var = msq - mean * mean;
        y = (y - mean) * rsqrtf(var + LN_EPS) * gg[j] + bb[j];
        y = fmaxf(y, 0.f);
        sy[tid] = y;
        __syncthreads();
        // layer 2: thread = output channel c
        float as = b2s[tid], at = b2t[tid];
        const float* w2sr = w2s + (size_t)tid * 128;
        const float* w2tr = w2t + (size_t)tid * 128;
#pragma unroll 4
        for (int jj = 0; jj < 128; jj++) {
            as = fmaf(sy[jj], w2sr[jj], as);
            at = fmaf(sy[128 + jj], w2tr[jj], at);
        }
        float delta = as - at;
        accx = fmaf(delta, g_rowd[n * CC + tid], accx);
        accd = fmaf(delta, delta, accd);
        __syncthreads();
    }
    accx = blocksum(accx, sbuf);
    accd = blocksum(accd, sbuf);
    if (tid == 0) {
        float rela = g_d2sum + 2.0f * accx + (float)HWSZ * accd;
        float loss = (ALPHA * g_fgsum + BETA * g_bgsum + GAMMA * g_maskloss + LAMB * rela)
                     * (1.0f / (float)NN);
        out[0] = loss;
    }
}

// ---------------- launch ----------------
extern "C" void kernel_launch(void* const* d_in, const int* in_sizes, int n_in,
                              void* d_out, int out_size) {
    const float* S   = (const float*)d_in[0];
    const float* T   = (const float*)d_in[1];
    const float* gt  = (const float*)d_in[2];
    const float* wms = (const float*)d_in[3];
    const float* bms = (const float*)d_in[4];
    const float* wmt = (const float*)d_in[5];
    const float* bmt = (const float*)d_in[6];
    const float* w1s = (const float*)d_in[7];
    const float* b1s = (const float*)d_in[8];
    const float* gs  = (const float*)d_in[9];
    const float* bes = (const float*)d_in[10];
    const float* w2s = (const float*)d_in[11];
    const float* b2s = (const float*)d_in[12];
    const float* w1t = (const float*)d_in[13];
    const float* b1t = (const float*)d_in[14];
    const float* gtl = (const float*)d_in[15];
    const float* bet = (const float*)d_in[16];
    const float* w2t = (const float*)d_in[17];
    const float* b2t = (const float*)d_in[18];

    k_init<<<8, 256>>>();
    dim3 gbig(HWSZ / 1024, NN);
    k_pass1<<<gbig, 256>>>(S, T, wms, bms, wmt, bmt);
    k_pass2a<<<NN, 256>>>();
    k_pass2b<<<NN, 512>>>(gt);
    k_pass3<<<gbig, 256>>>(S, T);
    k_pass4<<<1, 256>>>(w1s, b1s, gs, bes, w2s, b2s,
                        w1t, b1t, gtl, bet, w2t, b2t, (float*)d_out);
}

// round 4
// speedup vs baseline: 1.2119x; 1.2119x over previous
#include <cuda_runtime.h>

#define NN   8
#define CC   256
#define HH   128
#define WW   128
#define HWSZ 16384
#define NBOX 20
#define TEMP     0.5f
#define INVTEMP  2.0f
#define ALPHA    1e-3f
#define BETA     5e-4f
#define GAMMA    1e-3f
#define LAMB     5e-6f
#define IMGF     1024.0f
#define LN_EPS   1e-5f

// ---------------- scratch (static device memory) ----------------
__device__ float4 g_pp [NN * HWSZ];   // (fea_s, fea_t, cm_s, cm_t) per pixel
__device__ float4 g_smw[NN * HWSZ];   // (sm_s, sm_t, wfg, wbg) per pixel
__device__ float  g_mfg[NN * HWSZ];   // foreground mask value per pixel
__device__ float g_ch_s [NN * CC];
__device__ float g_ch_t [NN * CC];
__device__ float g_ctx_s[NN * CC];
__device__ float g_ctx_t[NN * CC];
__device__ float g_rowd [NN * CC];
__device__ float g_fgrow[NN * CC];
__device__ float g_bgrow[NN * CC];
__device__ float g_den[NN * 4];       // exp-sums: 2*fea_s, 2*fea_t, cm_s, cm_t
__device__ float g_bgc[NN];
__device__ float g_fgsum, g_bgsum, g_d2sum, g_maskloss;

// ---------------- reduction helpers ----------------
__device__ __forceinline__ float warpsum(float v) {
#pragma unroll
    for (int o = 16; o > 0; o >>= 1) v += __shfl_xor_sync(0xffffffffu, v, o);
    return v;
}
__device__ __forceinline__ float blocksum(float v, float* sbuf) {
    int tid = threadIdx.x, lane = tid & 31, warp = tid >> 5;
    int nw = blockDim.x >> 5;
    v = warpsum(v);
    if (lane == 0) sbuf[warp] = v;
    __syncthreads();
    if (warp == 0) {
        float r = (lane < nw) ? sbuf[lane] : 0.0f;
        r = warpsum(r);
        if (lane == 0) sbuf[0] = r;
    }
    __syncthreads();
    float r = sbuf[0];
    __syncthreads();
    return r;
}

// ---------------- init ----------------
__global__ void __launch_bounds__(256) k_init() {
    int i = blockIdx.x * blockDim.x + threadIdx.x;
    if (i < NN * CC) {
        g_ch_s[i] = 0.f; g_ch_t[i] = 0.f;
        g_ctx_s[i] = 0.f; g_ctx_t[i] = 0.f; g_rowd[i] = 0.f;
        g_fgrow[i] = 0.f; g_bgrow[i] = 0.f;
    }
    if (i < NN * 4) g_den[i] = 0.f;
    if (i < NN) g_bgc[i] = 0.f;
    if (i == 0) { g_fgsum = 0.f; g_bgsum = 0.f; g_d2sum = 0.f; g_maskloss = 0.f; }
}

// ---------------- pass1: stream S,T once -> per-pixel stats (no reductions) --
// grid (32, NN), block 256, thread owns 2 pixels (float2 loads)
__global__ void __launch_bounds__(256) k_pass1(
        const float* __restrict__ S, const float* __restrict__ T,
        const float* __restrict__ wms, const float* __restrict__ bms,
        const float* __restrict__ wmt, const float* __restrict__ bmt) {
    __shared__ float sws[CC], swt[CC];
    int tid = threadIdx.x;
    sws[tid] = wms[tid];
    swt[tid] = wmt[tid];
    __syncthreads();

    int n = blockIdx.y;
    int p = blockIdx.x * 512 + tid * 2;
    const float2* Sp = (const float2*)(S + (size_t)n * CC * HWSZ + p);
    const float2* Tp = (const float2*)(T + (size_t)n * CC * HWSZ + p);

    float2 fs = make_float2(0.f, 0.f), ft = fs, cs = fs, ct = fs;
#pragma unroll 8
    for (int c = 0; c < CC; c++) {
        float2 s = Sp[(size_t)c * (HWSZ / 2)];
        float2 t = Tp[(size_t)c * (HWSZ / 2)];
        fs.x += fabsf(s.x); fs.y += fabsf(s.y);
        ft.x += fabsf(t.x); ft.y += fabsf(t.y);
        float ws = sws[c], wt = swt[c];
        cs.x = fmaf(s.x, ws, cs.x); cs.y = fmaf(s.y, ws, cs.y);
        ct.x = fmaf(t.x, wt, ct.x); ct.y = fmaf(t.y, wt, ct.y);
    }
    const float invC = 1.0f / (float)CC;
    float bs = bms[0], bt = bmt[0];
    g_pp[n * HWSZ + p    ] = make_float4(fs.x * invC, ft.x * invC, cs.x + bs, ct.x + bt);
    g_pp[n * HWSZ + p + 1] = make_float4(fs.y * invC, ft.y * invC, cs.y + bs, ct.y + bt);
}

// ---------------- k_mask: rasterize boxes -> mfg per pixel -------------------
// grid (32, NN), block 256, thread owns 2 pixels
__global__ void __launch_bounds__(256) k_mask(const float* __restrict__ gt) {
    __shared__ float bhmin[NBOX], bhmax[NBOX], bwmin[NBOX], bwmax[NBOX], barea[NBOX];
    int n = blockIdx.y, tid = threadIdx.x;
    if (tid < NBOX) {
        const float* b = gt + ((size_t)n * NBOX + tid) * 4;
        float wmin = floorf(b[0] * ((float)WW / IMGF));
        float hmin = floorf(b[1] * ((float)HH / IMGF));
        float wmax = ceilf (b[2] * ((float)WW / IMGF));
        float hmax = ceilf (b[3] * ((float)HH / IMGF));
        bhmin[tid] = hmin; bhmax[tid] = hmax;
        bwmin[tid] = wmin; bwmax[tid] = wmax;
        barea[tid] = 1.0f / ((hmax + 1.0f - hmin) * (wmax + 1.0f - wmin));
    }
    __syncthreads();
    int p0 = blockIdx.x * 512 + tid * 2;
#pragma unroll
    for (int u = 0; u < 2; u++) {
        int p = p0 + u;
        float h = (float)(p >> 7), w = (float)(p & 127);
        float mfg = 0.f;
#pragma unroll 1
        for (int b = 0; b < NBOX; b++) {
            bool in = (h >= bhmin[b]) && (h <= bhmax[b]) && (w >= bwmin[b]) && (w <= bwmax[b]);
            if (in) mfg = fmaxf(mfg, barea[b]);
        }
        g_mfg[n * HWSZ + p] = mfg;
    }
}

// ---------------- k_sum: softmax denominators (no max pass) + bg count -------
// grid (32, NN), block 256, thread owns 2 pixels
__global__ void __launch_bounds__(256) k_sum() {
    __shared__ float sbuf[32];
    int n = blockIdx.y, tid = threadIdx.x;
    int p = blockIdx.x * 512 + tid * 2;
    float4 v0 = g_pp[n * HWSZ + p];
    float4 v1 = g_pp[n * HWSZ + p + 1];
    float m0 = g_mfg[n * HWSZ + p];
    float m1 = g_mfg[n * HWSZ + p + 1];
    float s0 = __expf(v0.x * INVTEMP) + __expf(v1.x * INVTEMP);
    float s1 = __expf(v0.y * INVTEMP) + __expf(v1.y * INVTEMP);
    float s2 = __expf(v0.z) + __expf(v1.z);
    float s3 = __expf(v0.w) + __expf(v1.w);
    float bg = (m0 == 0.f ? 1.f : 0.f) + (m1 == 0.f ? 1.f : 0.f);
    s0 = blocksum(s0, sbuf); s1 = blocksum(s1, sbuf);
    s2 = blocksum(s2, sbuf); s3 = blocksum(s3, sbuf);
    bg = blocksum(bg, sbuf);
    if (tid == 0) {
        atomicAdd(&g_den[n * 4 + 0], s0);
        atomicAdd(&g_den[n * 4 + 1], s1);
        atomicAdd(&g_den[n * 4 + 2], s2);
        atomicAdd(&g_den[n * 4 + 3], s3);
        atomicAdd(&g_bgc[n], bg);
    }
}

// ---------------- k_wgt: write packed per-pixel weights + |Ss-St| loss -------
// grid (32, NN), block 256, thread owns 2 pixels
__global__ void __launch_bounds__(256) k_wgt() {
    __shared__ float sbuf[32];
    int n = blockIdx.y, tid = threadIdx.x;
    int p = blockIdx.x * 512 + tid * 2;
    float r0 = 1.0f / g_den[n * 4 + 0];
    float r1 = 1.0f / g_den[n * 4 + 1];
    float r2 = 1.0f / g_den[n * 4 + 2];
    float r3 = 1.0f / g_den[n * 4 + 3];
    float bgc = g_bgc[n];
    float invbg = (bgc > 0.f) ? (1.0f / bgc) : 0.f;
    float sd = 0.f;
#pragma unroll
    for (int u = 0; u < 2; u++) {
        float4 v = g_pp[n * HWSZ + p + u];
        float mfg = g_mfg[n * HWSZ + p + u];
        float Ss  = (float)HWSZ * __expf(v.x * INVTEMP) * r0;
        float St  = (float)HWSZ * __expf(v.y * INVTEMP) * r1;
        float sms = __expf(v.z) * r2;
        float smt = __expf(v.w) * r3;
        float mbg = (mfg > 0.f) ? 0.f : invbg;
        g_smw[n * HWSZ + p + u] = make_float4(sms, smt, St * mfg, St * mbg);
        sd += fabsf(Ss - St);
    }
    sd = blocksum(sd, sbuf);
    if (tid == 0) atomicAdd(&g_maskloss, sd);
}

// ---------------- k_rowk: second stream of S,T -> ALL per-channel reductions -
// grid (CC/4, NN), block 512 (16 warps x 1024-pixel stripes), 4 channels/block
__global__ void __launch_bounds__(512) k_rowk(
        const float* __restrict__ S, const float* __restrict__ T) {
    int n = blockIdx.y;
    int c0 = blockIdx.x * 4;
    int tid = threadIdx.x, lane = tid & 31, warp = tid >> 5;
    float a_chs[4] = {0.f, 0.f, 0.f, 0.f};
    float a_cht[4] = {0.f, 0.f, 0.f, 0.f};
    float a_cxs[4] = {0.f, 0.f, 0.f, 0.f};
    float a_cxt[4] = {0.f, 0.f, 0.f, 0.f};
    float a_rd [4] = {0.f, 0.f, 0.f, 0.f};
    float a_fg [4] = {0.f, 0.f, 0.f, 0.f};
    float a_bg [4] = {0.f, 0.f, 0.f, 0.f};
    float d2a = 0.f;
    const float4* W = g_smw + n * HWSZ;
    const float* Sb = S + ((size_t)n * CC + c0) * HWSZ;
    const float* Tb = T + ((size_t)n * CC + c0) * HWSZ;
    int pbase = warp * 1024;

#pragma unroll 1
    for (int g = 0; g < 8; g++) {
        int p = pbase + g * 128 + lane * 4;
        float4 w0 = W[p], w1 = W[p + 1], w2 = W[p + 2], w3 = W[p + 3];
#pragma unroll
        for (int c = 0; c < 4; c++) {
            float4 s = *(const float4*)(Sb + (size_t)c * HWSZ + p);
            float4 t = *(const float4*)(Tb + (size_t)c * HWSZ + p);
            a_chs[c] += (fabsf(s.x) + fabsf(s.y)) + (fabsf(s.z) + fabsf(s.w));
            a_cht[c] += (fabsf(t.x) + fabsf(t.y)) + (fabsf(t.z) + fabsf(t.w));
            a_cxs[c] = fmaf(s.x, w0.x, fmaf(s.y, w1.x, fmaf(s.z, w2.x, fmaf(s.w, w3.x, a_cxs[c]))));
            a_cxt[c] = fmaf(t.x, w0.y, fmaf(t.y, w1.y, fmaf(t.z, w2.y, fmaf(t.w, w3.y, a_cxt[c]))));
            float dx = s.x - t.x, dy = s.y - t.y, dz = s.z - t.z, dw = s.w - t.w;
            a_rd[c] += (dx + dy) + (dz + dw);
            float ex = dx * dx, ey = dy * dy, ez = dz * dz, ew = dw * dw;
            d2a += (ex + ey) + (ez + ew);
            a_fg[c] = fmaf(ex, w0.z, fmaf(ey, w1.z, fmaf(ez, w2.z, fmaf(ew, w3.z, a_fg[c]))));
            a_bg[c] = fmaf(ex, w0.w, fmaf(ey, w1.w, fmaf(ez, w2.w, fmaf(ew, w3.w, a_bg[c]))));
        }
    }
#pragma unroll
    for (int c = 0; c < 4; c++) {
        int o = n * CC + c0 + c;
        float v;
        v = warpsum(a_chs[c]); if (lane == 0) atomicAdd(&g_ch_s[o], v);
        v = warpsum(a_cht[c]); if (lane == 0) atomicAdd(&g_ch_t[o], v);
        v = warpsum(a_cxs[c]); if (lane == 0) atomicAdd(&g_ctx_s[o], v);
        v = warpsum(a_cxt[c]); if (lane == 0) atomicAdd(&g_ctx_t[o], v);
        v = warpsum(a_rd [c]); if (lane == 0) atomicAdd(&g_rowd [o], v);
        v = warpsum(a_fg [c]); if (lane == 0) atomicAdd(&g_fgrow[o], v);
        v = warpsum(a_bg [c]); if (lane == 0) atomicAdd(&g_bgrow[o], v);
    }
    d2a = warpsum(d2a);
    if (lane == 0) atomicAdd(&g_d2sum, d2a);
}

// ---------------- k_chan: channel softmaxes + Ct-weighted fg/bg + mask term --
// grid NN, block 256 (thread = channel)
__global__ void __launch_bounds__(256) k_chan() {
    __shared__ float sbuf[32];
    int n = blockIdx.x, tid = threadIdx.x;
    const float sc = 1.0f / ((float)HWSZ * TEMP);
    float es = __expf(g_ch_s[n * CC + tid] * sc);
    float et = __expf(g_ch_t[n * CC + tid] * sc);
    float ss = blocksum(es, sbuf);
    float st = blocksum(et, sbuf);
    float Cs = (float)CC * es / ss;
    float Ct = (float)CC * et / st;
    float d   = blocksum(fabsf(Cs - Ct), sbuf);
    float fgp = blocksum(Ct * g_fgrow[n * CC + tid], sbuf);
    float bgp = blocksum(Ct * g_bgrow[n * CC + tid], sbuf);
    if (tid == 0) {
        atomicAdd(&g_maskloss, d);
        atomicAdd(&g_fgsum, fgp);
        atomicAdd(&g_bgsum, bgp);
    }
}

// ---------------- k_final: tiny MLPs + final scalar --------------------------
// grid 1, block 256
__global__ void __launch_bounds__(256) k_final(
        const float* __restrict__ w1s, const float* __restrict__ b1s,
        const float* __restrict__ gs,  const float* __restrict__ bes,
        const float* __restrict__ w2s, const float* __restrict__ b2s,
        const float* __restrict__ w1t, const float* __restrict__ b1t,
        const float* __restrict__ gtl, const float* __restrict__ bet,
        const float* __restrict__ w2t, const float* __restrict__ b2t,
        float* __restrict__ out) {
    __shared__ float sy[256];
    __shared__ float swsum[8], swsq[8];
    __shared__ float sbuf[32];
    int tid = threadIdx.x, lane = tid & 31, warp = tid >> 5;
    int j = tid & 127;
    bool isT = (tid >= 128);
    const float* w1 = isT ? w1t : w1s;
    const float* b1 = isT ? b1t : b1s;
    const float* gg = isT ? gtl : gs;
    const float* bb = isT ? bet : bes;
    const float* w1row = w1 + (size_t)j * CC;

    float accx = 0.f, accd = 0.f;
    for (int n = 0; n < NN; n++) {
        const float* ctx = (isT ? g_ctx_t : g_ctx_s) + n * CC;
        float y = b1[j];
#pragma unroll 4
        for (int c = 0; c < CC; c++) y = fmaf(ctx[c], w1row[c], y);
        float v = warpsum(y), v2 = warpsum(y * y);
        if (lane == 0) { swsum[warp] = v; swsq[warp] = v2; }
        __syncthreads();
        int h0 = isT ? 4 : 0;
        float mean = (swsum[h0] + swsum[h0 + 1] + swsum[h0 + 2] + swsum[h0 + 3]) * (1.0f / 128.0f);
        float msq  = (swsq[h0] + swsq[h0 + 1] + swsq[h0 + 2] + swsq[h0 + 3]) * (1.0f / 128.0f);
        float var = msq - mean * mean;
        y = (y - mean) * rsqrtf(var + LN_EPS) * gg[j] + bb[j];
        y = fmaxf(y, 0.f);
        sy[tid] = y;
        __syncthreads();
        float as = b2s[tid], at = b2t[tid];
        const float* w2sr = w2s + (size_t)tid * 128;
        const float* w2tr = w2t + (size_t)tid * 128;
#pragma unroll 4
        for (int jj = 0; jj < 128; jj++) {
            as = fmaf(sy[jj], w2sr[jj], as);
            at = fmaf(sy[128 + jj], w2tr[jj], at);
        }
        float delta = as - at;
        accx = fmaf(delta, g_rowd[n * CC + tid], accx);
        accd = fmaf(delta, delta, accd);
        __syncthreads();
    }
    accx = blocksum(accx, sbuf);
    accd = blocksum(accd, sbuf);
    if (tid == 0) {
        float rela = g_d2sum + 2.0f * accx + (float)HWSZ * accd;
        float loss = (ALPHA * g_fgsum + BETA * g_bgsum + GAMMA * g_maskloss + LAMB * rela)
                     * (1.0f / (float)NN);
        out[0] = loss;
    }
}

// ---------------- launch ----------------
extern "C" void kernel_launch(void* const* d_in, const int* in_sizes, int n_in,
                              void* d_out, int out_size) {
    const float* S   = (const float*)d_in[0];
    const float* T   = (const float*)d_in[1];
    const float* gt  = (const float*)d_in[2];
    const float* wms = (const float*)d_in[3];
    const float* bms = (const float*)d_in[4];
    const float* wmt = (const float*)d_in[5];
    const float* bmt = (const float*)d_in[6];
    const float* w1s = (const float*)d_in[7];
    const float* b1s = (const float*)d_in[8];
    const float* gs  = (const float*)d_in[9];
    const float* bes = (const float*)d_in[10];
    const float* w2s = (const float*)d_in[11];
    const float* b2s = (const float*)d_in[12];
    const float* w1t = (const float*)d_in[13];
    const float* b1t = (const float*)d_in[14];
    const float* gtl = (const float*)d_in[15];
    const float* bet = (const float*)d_in[16];
    const float* w2t = (const float*)d_in[17];
    const float* b2t = (const float*)d_in[18];

    dim3 gpix(32, NN);
    k_init <<<8, 256>>>();
    k_pass1<<<gpix, 256>>>(S, T, wms, bms, wmt, bmt);
    k_mask <<<gpix, 256>>>(gt);
    k_sum  <<<gpix, 256>>>();
    k_wgt  <<<gpix, 256>>>();
    k_rowk <<<dim3(CC / 4, NN), 512>>>(S, T);
    k_chan <<<NN, 256>>>();
    k_final<<<1, 256>>>(w1s, b1s, gs, bes, w2s, b2s,
                        w1t, b1t, gtl, bet, w2t, b2t, (float*)d_out);
}